// round 17
// baseline (speedup 1.0000x reference)
#include <cuda_runtime.h>

// EnergyGatedDeltaModel — GB300 sm_103a
// R16 = R15 arithmetic (bit-identical decisions: packed f32x2 NEON dots,
// fixed-point s32 redux fast gate, paired exact slow path) with THREE batches
// per warp (171 CTAs). Pair (0,1) uses the paired slow chain; batch 2 resolves
// single. Overhang slot (CTA 170, p=2) clamps to batch 511 and is masked from
// output + write count.

#define B_ 512
#define L_ 2048
#define H_ 32
#define V_ 64
#define STEPS (L_ - 1)
#define THRESH 1.0f
#define FIXSCALE 4096.0f
#define ROWP 36
#define NB 171            // CTAs; batches p*171 + blockIdx.x
// bank-parity layout (word offsets, all 16B-aligned):
#define OFF_MN0 0         // ≡0  mod 32
#define OFF_MN1 1168      // ≡16
#define OFF_MN2 2336      // ≡0
#define OFF_MOA 3504      // ≡16 (rebuild partner for mn≡0: batches 0,2)
#define OFF_MOB 4672      // ≡0  (rebuild partner for mn≡16: batch 1)
#define SLOWBUF_WORDS (OFF_MOB + H_ * ROWP)

typedef unsigned long long u64;

__device__ float g_table[V_ * H_];
__device__ float g_ksq[V_];
__device__ float g_denom[V_];
__device__ int   g_writes;

// ---- packed f32x2 primitives ----
__device__ __forceinline__ u64 pk2(float lo, float hi) {
    u64 r; asm("mov.b64 %0, {%1,%2};" : "=l"(r) : "f"(lo), "f"(hi)); return r;
}
__device__ __forceinline__ void upk2(float& lo, float& hi, u64 v) {
    asm("mov.b64 {%0,%1}, %2;" : "=f"(lo), "=f"(hi) : "l"(v));
}
__device__ __forceinline__ u64 mul2_(u64 a, u64 b) {
    u64 r; asm("mul.rn.f32x2 %0, %1, %2;" : "=l"(r) : "l"(a), "l"(b)); return r;
}
__device__ __forceinline__ u64 add2_(u64 a, u64 b) {
    u64 r; asm("add.rn.f32x2 %0, %1, %2;" : "=l"(r) : "l"(a), "l"(b)); return r;
}
__device__ __forceinline__ u64 fma2_(u64 a, u64 b, u64 c) {
    u64 r; asm("fma.rn.f32x2 %0, %1, %2, %3;" : "=l"(r) : "l"(a), "l"(b), "l"(c)); return r;
}

// Fixed-point redux fast-gate dE (classification only; error <= 0.14,
// certification margin vs THRESH=1.0 holds — see R15 analysis).
__device__ __forceinline__ float dE_fast(float u, float v, float ks, unsigned FULL) {
    const int i1 = __float2int_rn(__fmul_rn(u, v) * FIXSCALE);
    const int i2 = __float2int_rn(__fmul_rn(u, u) * FIXSCALE);
    const int s1 = __reduce_add_sync(FULL, i1);
    const int s2 = __reduce_add_sync(FULL, i2);
    const float suv = __int2float_rn(s1) * (1.0f / FIXSCALE);
    const float suu = __int2float_rn(s2) * (1.0f / FIXSCALE);
    return __fadd_rn(__fadd_rn(suv, suv), __fmul_rn(suu, ks));
}

// Packed NEON VF4xIC4 dot (per-element order identical to scalar neon_dot32).
__device__ __forceinline__ float dot2p(const u64* x2, const float* k) {
    const u64* y2 = (const u64*)k;
    u64 A2[8];
#pragma unroll
    for (int c = 0; c < 8; c++) A2[c] = mul2_(x2[c], y2[c]);
#pragma unroll
    for (int c = 0; c < 8; c++) A2[c] = fma2_(x2[8 + c], y2[8 + c], A2[c]);
    u64 W01 = add2_(add2_(add2_(A2[0], A2[2]), A2[4]), A2[6]);
    u64 W23 = add2_(add2_(add2_(A2[1], A2[3]), A2[5]), A2[7]);
    u64 R = add2_(W01, W23);
    float rl, rh; upk2(rl, rh, R);
    return __fadd_rn(rl, rh);
}

__device__ __forceinline__ float neon_sum32(const float* t) {
    float A[16];
#pragma unroll
    for (int c = 0; c < 16; c++) A[c] = __fadd_rn(t[c], t[16 + c]);
    float V[4];
#pragma unroll
    for (int l = 0; l < 4; l++)
        V[l] = __fadd_rn(__fadd_rn(__fadd_rn(A[l], A[4 + l]), A[8 + l]), A[12 + l]);
    return __fadd_rn(__fadd_rn(V[0], V[2]), __fadd_rn(V[1], V[3]));
}

// ---------------------------------------------------------------------------
__global__ void precompute_kernel(const float* __restrict__ embed,
                                  const float* __restrict__ w1,
                                  const float* __restrict__ b1,
                                  const float* __restrict__ w2,
                                  const float* __restrict__ b2,
                                  const float* __restrict__ ln_g,
                                  const float* __restrict__ ln_b)
{
    __shared__ float h_sh[H_];
    __shared__ float s_sh[2 * H_];
    __shared__ float x_sh[H_];

    const int v = blockIdx.x;
    const int t = threadIdx.x;
    if (v == 0 && t == 0) g_writes = 0;

    if (t < H_) h_sh[t] = embed[v * H_ + t];
    __syncthreads();

    {
        const int j = t;
        float s = 0.0f;
#pragma unroll
        for (int i = 0; i < H_; i++) s = fmaf(h_sh[i], w1[i * 2 * H_ + j], s);
        s = __fadd_rn(s, b1[j]);
        s_sh[j] = fmaxf(s, 0.0f);
    }
    __syncthreads();

    if (t < H_) {
        const int i = t;
        float acc = 0.0f;
#pragma unroll
        for (int j = 0; j < 2 * H_; j++) acc = fmaf(s_sh[j], w2[j * H_ + i], acc);
        float ff = __fadd_rn(acc, b2[i]);
        x_sh[i] = __fadd_rn(h_sh[i], ff);
    }
    __syncthreads();

    if (t == 0) {
        float x[H_], d[H_], sq[H_];
#pragma unroll
        for (int i = 0; i < H_; i++) x[i] = x_sh[i];
        float mu = __fmul_rn(neon_sum32(x), 1.0f / H_);
#pragma unroll
        for (int i = 0; i < H_; i++) {
            d[i] = __fsub_rn(x[i], mu);
            sq[i] = __fmul_rn(d[i], d[i]);
        }
        float var = __fmul_rn(neon_sum32(sq), 1.0f / H_);
        float rs = __fdiv_rn(1.0f, __fsqrt_rn(__fadd_rn(var, 1e-5f)));
        float y[H_];
#pragma unroll
        for (int i = 0; i < H_; i++) {
            y[i] = __fadd_rn(__fmul_rn(__fmul_rn(d[i], rs), ln_g[i]), ln_b[i]);
            g_table[v * H_ + i] = y[i];
            sq[i] = __fmul_rn(y[i], y[i]);
        }
        float ksq = neon_sum32(sq);
        g_ksq[v]   = ksq;
        g_denom[v] = __fadd_rn(ksq, 1e-6f);
    }
}

// ---------------------------------------------------------------------------
// Slow-path primitives (values identical to R11/R15).
// ---------------------------------------------------------------------------
__device__ __forceinline__ float chain64p(const float* P, int c) {
    float a = 0.0f;
#pragma unroll
    for (int g = 0; g < 4; g++) {
        float s[16];
#pragma unroll
        for (int i = 0; i < 16; i++) {
            const int m = g * 16 + i;
            s[i] = P[(m >> 1) * ROWP + (m & 1) * 16 + c];
        }
#pragma unroll
        for (int i = 0; i < 16; i++)
            a = fmaf(s[i], s[i], a);
    }
    return a;
}

__device__ __forceinline__ float fold16(float val, int base, unsigned FULL) {
    float V[4];
#pragma unroll
    for (int l = 0; l < 4; l++) {
        float a0 = __shfl_sync(FULL, val, base + l);
        float a1 = __shfl_sync(FULL, val, base + l + 4);
        float a2 = __shfl_sync(FULL, val, base + l + 8);
        float a3 = __shfl_sync(FULL, val, base + l + 12);
        V[l] = __fadd_rn(__fadd_rn(__fadd_rn(a0, a1), a2), a3);
    }
    return __fadd_rn(__fadd_rn(V[0], V[2]), __fadd_rn(V[1], V[3]));
}

__device__ __forceinline__ void store_row2(float* buf, int lane, const u64* M2) {
    ulonglong2* p = (ulonglong2*)(buf + lane * ROWP);
#pragma unroll
    for (int q = 0; q < 8; q++) {
        ulonglong2 v;
        v.x = M2[2 * q];
        v.y = M2[2 * q + 1];
        p[q] = v;
    }
}

__device__ __forceinline__ void store_row_mn2(float* buf, int lane, const u64* M2,
                                              u64 u2, const float* k) {
    const u64* k2 = (const u64*)k;
    ulonglong2* p = (ulonglong2*)(buf + lane * ROWP);
#pragma unroll
    for (int q = 0; q < 8; q++) {
        ulonglong2 v;
        v.x = fma2_(u2, k2[2 * q],     M2[2 * q]);
        v.y = fma2_(u2, k2[2 * q + 1], M2[2 * q + 1]);
        p[q] = v;
    }
}

__device__ __forceinline__ int resolve_single(const u64* M2, u64 u2, const float* k,
                                              float& eo, bool& valid,
                                              float* mnbuf, float* mobuf,
                                              int lane, unsigned FULL)
{
    int g;
    if (valid) {
        store_row_mn2(mnbuf, lane, M2, u2, k);
        __syncwarp();
        float a = 0.0f;
        if (lane < 16) a = chain64p(mnbuf, lane);
        __syncwarp();
        float en = fold16(a, 0, FULL);
        g = en > eo;
        if (g) eo = en;
    } else {
        store_row2(mobuf, lane, M2);
        store_row_mn2(mnbuf, lane, M2, u2, k);
        __syncwarp();
        float a = chain64p((lane < 16) ? mobuf : mnbuf, lane & 15);
        __syncwarp();
        float eoc = fold16(a, 0, FULL);
        float en  = fold16(a, 16, FULL);
        g = en > eoc;
        eo = g ? en : eoc;
        valid = true;
    }
    return g;
}

// ---------------------------------------------------------------------------
__global__ void __launch_bounds__(32, 1) scan_kernel(const int* __restrict__ seq,
                                                     const float* __restrict__ w_read,
                                                     const float* __restrict__ b_read,
                                                     const float* __restrict__ w_out,
                                                     const float* __restrict__ b_out,
                                                     float* __restrict__ out)
{
    __shared__ __align__(16) float tsh[V_ * H_];
    __shared__ __align__(16) float slowbuf[SLOWBUF_WORDS];
    __shared__ float dnsh[V_];
    __shared__ float kssh[V_];
    __shared__ int   toks[3][32];
    __shared__ float scratch[H_];

    const int lane = threadIdx.x;
    const unsigned FULL = 0xffffffffu;
    float* mn0 = slowbuf + OFF_MN0;
    float* mn1 = slowbuf + OFF_MN1;
    float* mn2 = slowbuf + OFF_MN2;
    float* moA = slowbuf + OFF_MOA;   // for batches 0 and 2 (mn≡0)
    float* moB = slowbuf + OFF_MOB;   // for batch 1 (mn≡16)

    for (int i = lane; i < V_ * H_; i += 32) tsh[i] = g_table[i];
    dnsh[lane]      = g_denom[lane];
    dnsh[lane + 32] = g_denom[lane + 32];
    kssh[lane]      = g_ksq[lane];
    kssh[lane + 32] = g_ksq[lane + 32];
    __syncwarp();

    // batch indices; overhang (512) clamps to 511 and is masked at the end
    int bb[3];
    bool bval[3];
#pragma unroll
    for (int p = 0; p < 3; p++) {
        int b = blockIdx.x + p * NB;
        bval[p] = (b < B_);
        bb[p] = bval[p] ? b : (B_ - 1);
    }

    u64 M2s[3][16];
#pragma unroll
    for (int p = 0; p < 3; p++)
#pragma unroll
        for (int j = 0; j < 16; j++) M2s[p][j] = 0ULL;

    float eo[3] = {0.0f, 0.0f, 0.0f};
    bool valid[3] = {true, true, true};
    int wr[3] = {0, 0, 0};

    const int* sb[3];
#pragma unroll
    for (int p = 0; p < 3; p++) sb[p] = seq + bb[p] * L_;

    for (int t0 = 0; t0 < STEPS; t0 += 32) {
#pragma unroll
        for (int p = 0; p < 3; p++) toks[p][lane] = sb[p][t0 + lane];
        __syncwarp();
        const int tend = (STEPS - t0) < 32 ? (STEPS - t0) : 32;

        for (int tt = 0; tt < tend; tt++) {
            const float* k[3];
            float dn[3], ks[3];
#pragma unroll
            for (int p = 0; p < 3; p++) {
                const int tok = toks[p][tt];
                k[p]  = tsh + tok * H_;
                dn[p] = dnsh[tok];
                ks[p] = kssh[tok];
            }

            float v[3], u[3], dE[3];
#pragma unroll
            for (int p = 0; p < 3; p++) v[p] = dot2p(M2s[p], k[p]);
#pragma unroll
            for (int p = 0; p < 3; p++)
                u[p] = __fsub_rn(k[p][lane], __fdiv_rn(v[p], dn[p]));
#pragma unroll
            for (int p = 0; p < 3; p++) dE[p] = dE_fast(u[p], v[p], ks[p], FULL);

            bool slow[3];
            int gate[3];
            u64 u2[3];
#pragma unroll
            for (int p = 0; p < 3; p++) {
                slow[p] = fabsf(dE[p]) < THRESH;
                gate[p] = dE[p] > 0.0f;
                u2[p] = pk2(u[p], u[p]);
            }

            if (slow[0] | slow[1]) {
                if (slow[0] & slow[1] & valid[0] & valid[1]) {
                    store_row_mn2(mn0, lane, M2s[0], u2[0], k[0]);
                    store_row_mn2(mn1, lane, M2s[1], u2[1], k[1]);
                    __syncwarp();
                    float a = chain64p((lane < 16) ? mn0 : mn1, lane & 15);
                    __syncwarp();
                    float en0 = fold16(a, 0, FULL);
                    float en1 = fold16(a, 16, FULL);
                    gate[0] = en0 > eo[0];
                    gate[1] = en1 > eo[1];
                    if (gate[0]) eo[0] = en0;
                    if (gate[1]) eo[1] = en1;
                } else {
                    if (slow[0])
                        gate[0] = resolve_single(M2s[0], u2[0], k[0], eo[0], valid[0],
                                                 mn0, moA, lane, FULL);
                    if (slow[1])
                        gate[1] = resolve_single(M2s[1], u2[1], k[1], eo[1], valid[1],
                                                 mn1, moB, lane, FULL);
                }
            }
            if (slow[2])
                gate[2] = resolve_single(M2s[2], u2[2], k[2], eo[2], valid[2],
                                         mn2, moA, lane, FULL);

#pragma unroll
            for (int p = 0; p < 3; p++) {
                if (gate[p]) {
                    wr[p]++;
                    const u64* k2 = (const u64*)k[p];
#pragma unroll
                    for (int j = 0; j < 16; j++)
                        M2s[p][j] = fma2_(u2[p], k2[j], M2s[p][j]);
                    if (!slow[p]) valid[p] = false;
                }
            }
        }
        __syncwarp();
    }

    // -------- readout (3 batches; overhang masked), identical arithmetic -----
#pragma unroll
    for (int pass = 0; pass < 3; pass++) {
        if (!bval[pass]) continue;
        const int b = bb[pass];
        const int qtok = sb[pass][L_ - 1];
        const float* qv = tsh + qtok * H_;
        float ctx = dot2p(M2s[pass], qv);

        scratch[lane] = ctx;
        __syncwarp();
        float rr = 0.0f;
#pragma unroll
        for (int j = 0; j < H_; j++) rr = fmaf(scratch[j], w_read[j * H_ + lane], rr);
        rr = __fadd_rn(rr, b_read[lane]);
        __syncwarp();
        scratch[lane] = rr;
        __syncwarp();

        float o0 = 0.0f, o1 = 0.0f;
#pragma unroll
        for (int j = 0; j < H_; j++) {
            const float rj = scratch[j];
            o0 = fmaf(rj, w_out[j * V_ + lane], o0);
            o1 = fmaf(rj, w_out[j * V_ + lane + H_], o1);
        }
        out[b * V_ + lane]      = __fadd_rn(o0, b_out[lane]);
        out[b * V_ + lane + H_] = __fadd_rn(o1, b_out[lane + H_]);
        __syncwarp();
    }

    if (lane == 0) {
        int w = (bval[0] ? wr[0] : 0) + (bval[1] ? wr[1] : 0) + (bval[2] ? wr[2] : 0);
        atomicAdd(&g_writes, w);
    }
}

// ---------------------------------------------------------------------------
__global__ void finalize_kernel(float* __restrict__ out, int out_size)
{
    if (out_size > B_ * V_)
        out[B_ * V_] = __fdiv_rn((float)g_writes, (float)(STEPS * B_));
}

extern "C" void kernel_launch(void* const* d_in, const int* in_sizes, int n_in,
                              void* d_out, int out_size)
{
    const int*   seq    = (const int*)d_in[0];
    const float* embed  = (const float*)d_in[1];
    const float* w1     = (const float*)d_in[2];
    const float* b1     = (const float*)d_in[3];
    const float* w2     = (const float*)d_in[4];
    const float* b2     = (const float*)d_in[5];
    const float* ln_g   = (const float*)d_in[6];
    const float* ln_b   = (const float*)d_in[7];
    const float* w_read = (const float*)d_in[8];
    const float* b_read = (const float*)d_in[9];
    const float* w_out  = (const float*)d_in[10];
    const float* b_out  = (const float*)d_in[11];
    float* out = (float*)d_out;

    precompute_kernel<<<V_, 64>>>(embed, w1, b1, w2, b2, ln_g, ln_b);
    scan_kernel<<<NB, 32>>>(seq, w_read, b_read, w_out, b_out, out);
    finalize_kernel<<<1, 1>>>(out, out_size);
}